// round 6
// baseline (speedup 1.0000x reference)
#include <cuda_runtime.h>
#include <cstdint>

// ---------------- problem constants ----------------
#define BB       64
#define TT       2048
#define RNN_DIM  1024
#define EMB_DIM  512
#define ATT_DIM  128
#define N_FILT   32
#define KSIZE    31
#define PADW     15
#define TILE_T   128
#define NSPLIT   16          // t-splits for context kernel

// ---------------- scratch (no cudaMalloc allowed) ----------------
__device__ float g_pq[BB * ATT_DIM];
__device__ float g_energies[BB * TT];
__device__ float g_w[BB * TT];
__device__ float g_partial[BB * NSPLIT * EMB_DIM];

// ---------------- helpers ----------------
__device__ __forceinline__ float2 fma2(float2 a, float2 b, float2 c) {
    // d = a*b + c, packed f32x2 (Blackwell). ptxas won't emit this from C++.
    unsigned long long ra = *reinterpret_cast<unsigned long long*>(&a);
    unsigned long long rb = *reinterpret_cast<unsigned long long*>(&b);
    unsigned long long rc = *reinterpret_cast<unsigned long long*>(&c);
    unsigned long long rd;
    asm("fma.rn.f32x2 %0, %1, %2, %3;" : "=l"(rd) : "l"(ra), "l"(rb), "l"(rc));
    return *reinterpret_cast<float2*>(&rd);
}

__device__ __forceinline__ float tanh_fast(float x) {
    // tanh(x) = 1 - 2/(exp(2x)+1); exact limits at +/-inf, ~1e-6 rel err.
    float e = __expf(2.0f * x);
    return 1.0f - __fdividef(2.0f, e + 1.0f);
}

__device__ __forceinline__ float warp_max(float x) {
    #pragma unroll
    for (int o = 16; o; o >>= 1) x = fmaxf(x, __shfl_xor_sync(0xffffffffu, x, o));
    return x;
}
__device__ __forceinline__ float warp_sum(float x) {
    #pragma unroll
    for (int o = 16; o; o >>= 1) x += __shfl_xor_sync(0xffffffffu, x, o);
    return x;
}

// ---------------- K1: pq = hidden @ Wq^T  (B x 128) ----------------
__global__ void pq_kernel(const float* __restrict__ hidden,
                          const float* __restrict__ Wq) {
    int b = blockIdx.x;
    __shared__ float4 h4[RNN_DIM / 4];
    const float4* hsrc = reinterpret_cast<const float4*>(hidden + (size_t)b * RNN_DIM);
    for (int i = threadIdx.x; i < RNN_DIM / 4; i += blockDim.x) h4[i] = hsrc[i];
    __syncthreads();

    int warp = threadIdx.x >> 5, lane = threadIdx.x & 31;
    for (int j = 0; j < 32; j++) {
        int d = warp * 32 + j;
        const float4* wq4 = reinterpret_cast<const float4*>(Wq + (size_t)d * RNN_DIM);
        float s = 0.f;
        #pragma unroll
        for (int kk = lane; kk < RNN_DIM / 4; kk += 32) {
            float4 q = wq4[kk], h = h4[kk];
            s += q.x * h.x + q.y * h.y + q.z * h.z + q.w * h.w;
        }
        s = warp_sum(s);
        if (lane == 0) g_pq[b * ATT_DIM + d] = s;
    }
}

// ---------------- K2: fused conv + projection + tanh + energy ----------------
// grid: (T/TILE_T, B), 256 threads
__global__ __launch_bounds__(256) void energies_kernel(
    const float* __restrict__ aw, const float* __restrict__ awc,
    const float* __restrict__ pm, const float* __restrict__ conv_w,
    const float* __restrict__ Wd, const float* __restrict__ Wv)
{
    const int b = blockIdx.y;
    const int t0 = blockIdx.x * TILE_T;
    const int tid = threadIdx.x;
    const int CATW = TILE_T + KSIZE - 1;   // 158

    __shared__ float  cat_s[2 * (TILE_T + KSIZE - 1)];
    __shared__ float  convw_s[N_FILT * 2 * KSIZE];
    __shared__ float  wdt_s[N_FILT * ATT_DIM];      // [f][d] = Wd[d][f]
    __shared__ float  pq_s[ATT_DIM];
    __shared__ float  wv_s[ATT_DIM];
    __shared__ float2 loc2_s[N_FILT * (TILE_T / 2)]; // t-paired conv output

    for (int idx = tid; idx < 2 * CATW; idx += 256) {
        int c = idx / CATW, i = idx - c * CATW;
        int t = t0 - PADW + i;
        float v = 0.f;
        if (t >= 0 && t < TT) v = (c == 0 ? aw : awc)[(size_t)b * TT + t];
        cat_s[idx] = v;
    }
    for (int idx = tid; idx < N_FILT * 2 * KSIZE; idx += 256) convw_s[idx] = conv_w[idx];
    for (int idx = tid; idx < N_FILT * ATT_DIM; idx += 256) {
        int f = idx >> 7, d = idx & 127;
        wdt_s[idx] = Wd[d * N_FILT + f];
    }
    if (tid < ATT_DIM) { pq_s[tid] = g_pq[b * ATT_DIM + tid]; wv_s[tid] = Wv[tid]; }
    __syncthreads();

    // ---- Phase A: conv. Each thread: one filter f, 16 consecutive t. ----
    {
        int f = tid >> 3;
        int tl0 = (tid & 7) * 16;
        float acc[16];
        #pragma unroll
        for (int i = 0; i < 16; i++) acc[i] = 0.f;
        #pragma unroll
        for (int c = 0; c < 2; c++) {
            float win[46];
            #pragma unroll
            for (int i = 0; i < 46; i++) win[i] = cat_s[c * CATW + tl0 + i];
            #pragma unroll
            for (int k = 0; k < KSIZE; k++) {
                float w = convw_s[f * (2 * KSIZE) + c * KSIZE + k];
                #pragma unroll
                for (int t = 0; t < 16; t++) acc[t] = fmaf(w, win[t + k], acc[t]);
            }
        }
        #pragma unroll
        for (int j = 0; j < 8; j++)
            loc2_s[f * (TILE_T / 2) + (tl0 >> 1) + j] = make_float2(acc[2 * j], acc[2 * j + 1]);
    }
    __syncthreads();

    // ---- Phase B: per warp 16 t's (8 t-pairs). lane covers d = lane + 32i. ----
    const int warp = tid >> 5, lane = tid & 31;
    const int tpb = warp * 8;

    float2 acc2[4][8];
    #pragma unroll
    for (int i = 0; i < 4; i++)
        #pragma unroll
        for (int j = 0; j < 8; j++) acc2[i][j] = make_float2(0.f, 0.f);

    #pragma unroll 4
    for (int f = 0; f < N_FILT; f++) {
        float wd[4];
        #pragma unroll
        for (int i = 0; i < 4; i++) wd[i] = wdt_s[f * ATT_DIM + lane + 32 * i];
        float2 l2[8];
        #pragma unroll
        for (int j = 0; j < 8; j++) l2[j] = loc2_s[f * (TILE_T / 2) + tpb + j];
        #pragma unroll
        for (int i = 0; i < 4; i++) {
            float2 w2 = make_float2(wd[i], wd[i]);
            #pragma unroll
            for (int j = 0; j < 8; j++) acc2[i][j] = fma2(w2, l2[j], acc2[i][j]);
        }
    }

    const float* pmB = pm + ((size_t)b * TT + t0) * ATT_DIM;
    float2 e2[8];
    #pragma unroll
    for (int j = 0; j < 8; j++) e2[j] = make_float2(0.f, 0.f);

    #pragma unroll
    for (int i = 0; i < 4; i++) {
        int d = lane + 32 * i;
        float pqv = pq_s[d];
        float wvv = wv_s[d];
        #pragma unroll
        for (int j = 0; j < 8; j++) {
            int tl = (tpb + j) * 2;
            float x0 = acc2[i][j].x + pqv + pmB[(size_t)tl * ATT_DIM + d];
            float x1 = acc2[i][j].y + pqv + pmB[(size_t)(tl + 1) * ATT_DIM + d];
            e2[j].x += wvv * tanh_fast(x0);
            e2[j].y += wvv * tanh_fast(x1);
        }
    }

    #pragma unroll
    for (int j = 0; j < 8; j++) {
        float ex = warp_sum(e2[j].x);
        float ey = warp_sum(e2[j].y);
        if (lane == 0) {
            int tl = (tpb + j) * 2;
            *reinterpret_cast<float2*>(&g_energies[(size_t)b * TT + t0 + tl]) = make_float2(ex, ey);
        }
    }
}

// ---------------- K3: per-batch softmax over T ----------------
__global__ void softmax_kernel(const unsigned char* __restrict__ mask) {
    const int b = blockIdx.x, tid = threadIdx.x;  // 256 threads
    const int warp = tid >> 5, lane = tid & 31;
    __shared__ float red_m[8];
    __shared__ float red_s[8];
    __shared__ float s_max, s_sum;

    float v[8];
    #pragma unroll
    for (int i = 0; i < 8; i++) {
        int t = tid + 256 * i;
        float e = g_energies[(size_t)b * TT + t];
        if (mask[(size_t)b * TT + t]) e = __int_as_float(0xff800000);  // -inf
        v[i] = e;
    }

    float m = v[0];
    #pragma unroll
    for (int i = 1; i < 8; i++) m = fmaxf(m, v[i]);
    m = warp_max(m);
    if (lane == 0) red_m[warp] = m;
    __syncthreads();
    if (warp == 0) {
        float t = (lane < 8) ? red_m[lane] : __int_as_float(0xff800000);
        t = warp_max(t);
        if (lane == 0) s_max = t;
    }
    __syncthreads();
    const float M = s_max;

    float s = 0.f;
    #pragma unroll
    for (int i = 0; i < 8; i++) s += __expf(v[i] - M);
    s = warp_sum(s);
    if (lane == 0) red_s[warp] = s;
    __syncthreads();
    if (warp == 0) {
        float t = (lane < 8) ? red_s[lane] : 0.f;
        t = warp_sum(t);
        if (lane == 0) s_sum = t;
    }
    __syncthreads();
    const float inv = 1.0f / s_sum;

    #pragma unroll
    for (int i = 0; i < 8; i++) {
        int t = tid + 256 * i;
        g_w[(size_t)b * TT + t] = __expf(v[i] - M) * inv;
    }
}

// ---------------- K4: context partials, t-split ----------------
// grid: (NSPLIT, B), 128 threads; each thread one float4 column chunk.
__global__ __launch_bounds__(128) void context_kernel(const float* __restrict__ memory) {
    const int b = blockIdx.y, s = blockIdx.x;
    const int tid = threadIdx.x;
    const int TSEG = TT / NSPLIT;       // 128
    __shared__ float ws[TSEG];
    const int t0 = s * TSEG;
    ws[tid] = g_w[(size_t)b * TT + t0 + tid];
    __syncthreads();

    const float4* m4 = reinterpret_cast<const float4*>(memory + ((size_t)b * TT + t0) * EMB_DIM);
    float4 acc = make_float4(0.f, 0.f, 0.f, 0.f);
    #pragma unroll 8
    for (int t = 0; t < TSEG; t++) {
        float w = ws[t];
        float4 mv = m4[(size_t)t * (EMB_DIM / 4) + tid];
        acc.x += w * mv.x; acc.y += w * mv.y; acc.z += w * mv.z; acc.w += w * mv.w;
    }
    reinterpret_cast<float4*>(g_partial)[((size_t)(b * NSPLIT + s)) * (EMB_DIM / 4) + tid] = acc;
}

// ---------------- K5: reduce partials ----------------
__global__ void reduce_kernel(float* __restrict__ out) {
    int idx = blockIdx.x * blockDim.x + threadIdx.x;
    if (idx < BB * EMB_DIM) {
        int b = idx / EMB_DIM, e = idx - b * EMB_DIM;
        float s = 0.f;
        #pragma unroll
        for (int k = 0; k < NSPLIT; k++) s += g_partial[(b * NSPLIT + k) * EMB_DIM + e];
        out[idx] = s;
    }
}

// ---------------- launch ----------------
extern "C" void kernel_launch(void* const* d_in, const int* in_sizes, int n_in,
                              void* d_out, int out_size) {
    const float*         hidden = (const float*)d_in[0];          // (B, RNN_DIM)
    const float*         memory = (const float*)d_in[1];          // (B, T, EMB_DIM)
    const float*         pm     = (const float*)d_in[2];          // (B, T, ATT_DIM)
    const float*         aw     = (const float*)d_in[3];          // (B, T)
    const float*         awc    = (const float*)d_in[4];          // (B, T)
    const float*         Wq     = (const float*)d_in[5];          // (ATT_DIM, RNN_DIM)
    const float*         conv_w = (const float*)d_in[6];          // (N_FILT, 2, KSIZE)
    const float*         Wd     = (const float*)d_in[7];          // (ATT_DIM, N_FILT)
    const float*         Wv     = (const float*)d_in[8];          // (ATT_DIM,)
    const unsigned char* mask   = (const unsigned char*)d_in[9];  // (B, T) bool
    float* out = (float*)d_out;

    pq_kernel<<<BB, 128>>>(hidden, Wq);

    dim3 g2(TT / TILE_T, BB);
    energies_kernel<<<g2, 256>>>(aw, awc, pm, conv_w, Wd, Wv);

    softmax_kernel<<<BB, 256>>>(mask);

    dim3 g4(NSPLIT, BB);
    context_kernel<<<g4, 128>>>(memory);

    reduce_kernel<<<(BB * EMB_DIM + 255) / 256, 256>>>(out);
}

// round 7
// speedup vs baseline: 1.3150x; 1.3150x over previous
#include <cuda_runtime.h>
#include <cstdint>

// ---------------- problem constants ----------------
#define BB       64
#define TT       2048
#define RNN_DIM  1024
#define EMB_DIM  512
#define ATT_DIM  128
#define N_FILT   32
#define KSIZE    31
#define PADW     15
#define TILE_T   128
#define NSPLIT   32          // t-splits for context kernel
#define NTAPS    62          // 2 channels x 31 taps

// ---------------- scratch (no cudaMalloc allowed) ----------------
__device__ float g_pq[BB * ATT_DIM];
__device__ float g_G[NTAPS * ATT_DIM];       // fused conv x Wd matrix
__device__ float g_energies[BB * TT];
__device__ float g_w[BB * TT];
__device__ float g_partial[BB * NSPLIT * EMB_DIM];

// ---------------- helpers ----------------
__device__ __forceinline__ float2 fma2(float2 a, float2 b, float2 c) {
    unsigned long long ra = *reinterpret_cast<unsigned long long*>(&a);
    unsigned long long rb = *reinterpret_cast<unsigned long long*>(&b);
    unsigned long long rc = *reinterpret_cast<unsigned long long*>(&c);
    unsigned long long rd;
    asm("fma.rn.f32x2 %0, %1, %2, %3;" : "=l"(rd) : "l"(ra), "l"(rb), "l"(rc));
    return *reinterpret_cast<float2*>(&rd);
}

__device__ __forceinline__ float tanh_hw(float x) {
    float y;
    asm("tanh.approx.f32 %0, %1;" : "=f"(y) : "f"(x));
    return y;
}

__device__ __forceinline__ float warp_max(float x) {
    #pragma unroll
    for (int o = 16; o; o >>= 1) x = fmaxf(x, __shfl_xor_sync(0xffffffffu, x, o));
    return x;
}
__device__ __forceinline__ float warp_sum(float x) {
    #pragma unroll
    for (int o = 16; o; o >>= 1) x += __shfl_xor_sync(0xffffffffu, x, o);
    return x;
}

// ---------------- K0: G[(c,k),d] = sum_f conv_w[f,c,k] * Wd[d,f] ----------------
// grid 2 (c), 128 threads (d)
__global__ void G_kernel(const float* __restrict__ conv_w,
                         const float* __restrict__ Wd) {
    const int c = blockIdx.x, d = threadIdx.x;
    __shared__ float cw[N_FILT * KSIZE];   // [f][k] for this channel
    for (int i = threadIdx.x; i < N_FILT * KSIZE; i += 128) {
        int f = i / KSIZE, k = i - f * KSIZE;
        cw[i] = conv_w[(f * 2 + c) * KSIZE + k];
    }
    float wdrow[N_FILT];
    #pragma unroll
    for (int f = 0; f < N_FILT; f++) wdrow[f] = Wd[d * N_FILT + f];
    __syncthreads();

    #pragma unroll 4
    for (int k = 0; k < KSIZE; k++) {
        float s = 0.f;
        #pragma unroll
        for (int f = 0; f < N_FILT; f++) s = fmaf(cw[f * KSIZE + k], wdrow[f], s);
        g_G[(c * KSIZE + k) * ATT_DIM + d] = s;
    }
}

// ---------------- K1: pq = hidden @ Wq^T ----------------
// grid (4, B), 128 threads; block covers 32 d's, warp does 8 d serially
__global__ void pq_kernel(const float* __restrict__ hidden,
                          const float* __restrict__ Wq) {
    const int b = blockIdx.y;
    __shared__ float4 h4[RNN_DIM / 4];
    const float4* hsrc = reinterpret_cast<const float4*>(hidden + (size_t)b * RNN_DIM);
    for (int i = threadIdx.x; i < RNN_DIM / 4; i += 128) h4[i] = hsrc[i];
    __syncthreads();

    const int warp = threadIdx.x >> 5, lane = threadIdx.x & 31;
    #pragma unroll
    for (int jj = 0; jj < 8; jj++) {
        int d = blockIdx.x * 32 + warp * 8 + jj;
        const float4* wq4 = reinterpret_cast<const float4*>(Wq + (size_t)d * RNN_DIM);
        float s = 0.f;
        #pragma unroll
        for (int kk = 0; kk < 8; kk++) {
            float4 q = wq4[lane + 32 * kk], h = h4[lane + 32 * kk];
            s += q.x * h.x + q.y * h.y + q.z * h.z + q.w * h.w;
        }
        s = warp_sum(s);
        if (lane == 0) g_pq[b * ATT_DIM + d] = s;
    }
}

// ---------------- K2: fused stencil-GEMM + tanh + energy ----------------
// energies[b,t] = sum_d Wv[d] * tanh( pq[b,d] + pm[b,t,d] + sum_tap cat[c,t+k-15]*G[tap,d] )
// grid (T/TILE_T, B), 512 threads (16 warps). Warp w -> t = t0 + 8w .. +7.
// Lane owns d = 4*lane .. 4*lane+3.
__global__ __launch_bounds__(512, 1) void energies_kernel(
    const float* __restrict__ aw, const float* __restrict__ awc,
    const float* __restrict__ pm, const float* __restrict__ Wv)
{
    const int b  = blockIdx.y;
    const int t0 = blockIdx.x * TILE_T;
    const int tid = threadIdx.x;
    const int warp = tid >> 5, lane = tid & 31;
    const int wt0 = warp * 8;

    __shared__ __align__(16) float G_s[NTAPS * ATT_DIM];   // 31744 B
    __shared__ __align__(16) float cat_s[2][160];          // window 158 used
    __shared__ __align__(16) float pq_s[ATT_DIM];
    __shared__ __align__(16) float wv_s[ATT_DIM];

    for (int i = tid; i < NTAPS * ATT_DIM; i += 512) G_s[i] = g_G[i];
    for (int i = tid; i < 2 * 158; i += 512) {
        int c = i / 158, ii = i - c * 158;
        int t = t0 - PADW + ii;
        float v = 0.f;
        if (t >= 0 && t < TT) v = (c == 0 ? aw : awc)[(size_t)b * TT + t];
        cat_s[c][ii] = v;
    }
    if (tid < ATT_DIM) { pq_s[tid] = g_pq[b * ATT_DIM + tid]; wv_s[tid] = Wv[tid]; }
    __syncthreads();

    // accumulators: 8 t's x float4(d), stored as float2 pairs; init with pq
    float2 accA[8], accB[8];
    {
        float4 pq4 = reinterpret_cast<const float4*>(pq_s)[lane];
        #pragma unroll
        for (int j = 0; j < 8; j++) {
            accA[j] = make_float2(pq4.x, pq4.y);
            accB[j] = make_float2(pq4.z, pq4.w);
        }
    }

    const float4* Gs4 = reinterpret_cast<const float4*>(G_s);

    #pragma unroll
    for (int c = 0; c < 2; c++) {
        const float4* c4 = reinterpret_cast<const float4*>(&cat_s[c][0]);
        #pragma unroll
        for (int kb = 0; kb < 8; kb++) {
            const int k0 = kb * 4;
            const int NT = (kb == 7) ? 3 : 4;
            // window: cat[wt0+k0 .. wt0+k0+11], 16B aligned, broadcast
            const int base = (wt0 + k0) >> 2;
            float4 a0 = c4[base], a1 = c4[base + 1], a2 = c4[base + 2];
            float w[12] = {a0.x, a0.y, a0.z, a0.w,
                           a1.x, a1.y, a1.z, a1.w,
                           a2.x, a2.y, a2.z, a2.w};
            float2 w2[11];
            #pragma unroll
            for (int i = 0; i < 11; i++) w2[i] = make_float2(w[i], w[i]);

            #pragma unroll
            for (int dlt = 0; dlt < NT; dlt++) {
                const int tap = c * KSIZE + k0 + dlt;
                float4 g = Gs4[tap * 32 + lane];
                float2 gA = make_float2(g.x, g.y);
                float2 gB = make_float2(g.z, g.w);
                #pragma unroll
                for (int j = 0; j < 8; j++) {
                    accA[j] = fma2(gA, w2[dlt + j], accA[j]);
                    accB[j] = fma2(gB, w2[dlt + j], accB[j]);
                }
            }
        }
    }

    // epilogue: + pm, tanh, dot with Wv, warp-reduce over d
    const float4 wv4 = reinterpret_cast<const float4*>(wv_s)[lane];
    const float4* pm4 = reinterpret_cast<const float4*>(pm);

    #pragma unroll
    for (int j = 0; j < 8; j++) {
        int t = t0 + wt0 + j;
        float4 pmv = pm4[((size_t)b * TT + t) * 32 + lane];
        float x0 = tanh_hw(accA[j].x + pmv.x);
        float x1 = tanh_hw(accA[j].y + pmv.y);
        float x2 = tanh_hw(accB[j].x + pmv.z);
        float x3 = tanh_hw(accB[j].y + pmv.w);
        float p = x0 * wv4.x + x1 * wv4.y + x2 * wv4.z + x3 * wv4.w;
        p = warp_sum(p);
        if (lane == 0) g_energies[(size_t)b * TT + t] = p;
    }
}

// ---------------- K3: per-batch softmax over T ----------------
__global__ void softmax_kernel(const unsigned char* __restrict__ mask) {
    const int b = blockIdx.x, tid = threadIdx.x;  // 256 threads
    const int warp = tid >> 5, lane = tid & 31;
    __shared__ float red_m[8];
    __shared__ float red_s[8];
    __shared__ float s_max, s_sum;

    float v[8];
    #pragma unroll
    for (int i = 0; i < 8; i++) {
        int t = tid + 256 * i;
        float e = g_energies[(size_t)b * TT + t];
        if (mask[(size_t)b * TT + t]) e = __int_as_float(0xff800000);  // -inf
        v[i] = e;
    }

    float m = v[0];
    #pragma unroll
    for (int i = 1; i < 8; i++) m = fmaxf(m, v[i]);
    m = warp_max(m);
    if (lane == 0) red_m[warp] = m;
    __syncthreads();
    if (warp == 0) {
        float t = (lane < 8) ? red_m[lane] : __int_as_float(0xff800000);
        t = warp_max(t);
        if (lane == 0) s_max = t;
    }
    __syncthreads();
    const float M = s_max;

    float s = 0.f;
    #pragma unroll
    for (int i = 0; i < 8; i++) s += __expf(v[i] - M);
    s = warp_sum(s);
    if (lane == 0) red_s[warp] = s;
    __syncthreads();
    if (warp == 0) {
        float t = (lane < 8) ? red_s[lane] : 0.f;
        t = warp_sum(t);
        if (lane == 0) s_sum = t;
    }
    __syncthreads();
    const float inv = 1.0f / s_sum;

    #pragma unroll
    for (int i = 0; i < 8; i++) {
        int t = tid + 256 * i;
        g_w[(size_t)b * TT + t] = __expf(v[i] - M) * inv;
    }
}

// ---------------- K4: context partials, t-split ----------------
// grid (NSPLIT, B), 128 threads; thread = one float4 column chunk
__global__ __launch_bounds__(128) void context_kernel(const float* __restrict__ memory) {
    const int b = blockIdx.y, s = blockIdx.x;
    const int tid = threadIdx.x;
    const int TSEG = TT / NSPLIT;       // 64
    __shared__ float ws[TSEG];
    const int t0 = s * TSEG;
    if (tid < TSEG) ws[tid] = g_w[(size_t)b * TT + t0 + tid];
    __syncthreads();

    const float4* m4 = reinterpret_cast<const float4*>(memory + ((size_t)b * TT + t0) * EMB_DIM);
    float4 acc = make_float4(0.f, 0.f, 0.f, 0.f);
    #pragma unroll 16
    for (int t = 0; t < TSEG; t++) {
        float w = ws[t];
        float4 mv = m4[(size_t)t * (EMB_DIM / 4) + tid];
        acc.x += w * mv.x; acc.y += w * mv.y; acc.z += w * mv.z; acc.w += w * mv.w;
    }
    reinterpret_cast<float4*>(g_partial)[((size_t)(b * NSPLIT + s)) * (EMB_DIM / 4) + tid] = acc;
}

// ---------------- K5: reduce partials ----------------
__global__ void reduce_kernel(float* __restrict__ out) {
    int idx = blockIdx.x * blockDim.x + threadIdx.x;
    if (idx < BB * EMB_DIM) {
        int b = idx / EMB_DIM, e = idx - b * EMB_DIM;
        float s = 0.f;
        #pragma unroll
        for (int k = 0; k < NSPLIT; k++) s += g_partial[(b * NSPLIT + k) * EMB_DIM + e];
        out[idx] = s;
    }
}

// ---------------- launch ----------------
extern "C" void kernel_launch(void* const* d_in, const int* in_sizes, int n_in,
                              void* d_out, int out_size) {
    const float*         hidden = (const float*)d_in[0];          // (B, RNN_DIM)
    const float*         memory = (const float*)d_in[1];          // (B, T, EMB_DIM)
    const float*         pm     = (const float*)d_in[2];          // (B, T, ATT_DIM)
    const float*         aw     = (const float*)d_in[3];          // (B, T)
    const float*         awc    = (const float*)d_in[4];          // (B, T)
    const float*         Wq     = (const float*)d_in[5];          // (ATT_DIM, RNN_DIM)
    const float*         conv_w = (const float*)d_in[6];          // (N_FILT, 2, KSIZE)
    const float*         Wd     = (const float*)d_in[7];          // (ATT_DIM, N_FILT)
    const float*         Wv     = (const float*)d_in[8];          // (ATT_DIM,)
    const unsigned char* mask   = (const unsigned char*)d_in[9];  // (B, T) bool
    float* out = (float*)d_out;

    G_kernel<<<2, 128>>>(conv_w, Wd);

    dim3 g1(4, BB);
    pq_kernel<<<g1, 128>>>(hidden, Wq);

    dim3 g2(TT / TILE_T, BB);
    energies_kernel<<<g2, 512>>>(aw, awc, pm, Wv);

    softmax_kernel<<<BB, 256>>>(mask);

    dim3 g4(NSPLIT, BB);
    context_kernel<<<g4, 128>>>(memory);

    reduce_kernel<<<(BB * EMB_DIM + 255) / 256, 256>>>(out);
}

// round 8
// speedup vs baseline: 1.3236x; 1.0065x over previous
#include <cuda_runtime.h>
#include <cstdint>

// ---------------- problem constants ----------------
#define BB       64
#define TT       2048
#define RNN_DIM  1024
#define EMB_DIM  512
#define ATT_DIM  128
#define N_FILT   32
#define KSIZE    31
#define PADW     15
#define TILE_T   128
#define NSPLIT   32          // t-splits for context kernel
#define NTAPS    62          // 2 channels x 31 taps

// ---------------- scratch (no cudaMalloc allowed) ----------------
__device__ float g_pq[BB * ATT_DIM];
__device__ float g_G[NTAPS * ATT_DIM];       // fused conv x Wd matrix
__device__ float g_energies[BB * TT];
__device__ float g_w[BB * TT];
__device__ float g_partial[BB * NSPLIT * EMB_DIM];

// ---------------- helpers ----------------
__device__ __forceinline__ float2 fma2(float2 a, float2 b, float2 c) {
    unsigned long long ra = *reinterpret_cast<unsigned long long*>(&a);
    unsigned long long rb = *reinterpret_cast<unsigned long long*>(&b);
    unsigned long long rc = *reinterpret_cast<unsigned long long*>(&c);
    unsigned long long rd;
    asm("fma.rn.f32x2 %0, %1, %2, %3;" : "=l"(rd) : "l"(ra), "l"(rb), "l"(rc));
    return *reinterpret_cast<float2*>(&rd);
}

__device__ __forceinline__ float tanh_hw(float x) {
    float y;
    asm("tanh.approx.f32 %0, %1;" : "=f"(y) : "f"(x));
    return y;
}

__device__ __forceinline__ float warp_max(float x) {
    #pragma unroll
    for (int o = 16; o; o >>= 1) x = fmaxf(x, __shfl_xor_sync(0xffffffffu, x, o));
    return x;
}
__device__ __forceinline__ float warp_sum(float x) {
    #pragma unroll
    for (int o = 16; o; o >>= 1) x += __shfl_xor_sync(0xffffffffu, x, o);
    return x;
}

// ---------------- K0: G[(c,k),d] = sum_f conv_w[f,c,k] * Wd[d,f] ----------------
// grid 2 (c), 128 threads (d)
__global__ void G_kernel(const float* __restrict__ conv_w,
                         const float* __restrict__ Wd) {
    const int c = blockIdx.x, d = threadIdx.x;
    __shared__ float cw[N_FILT * KSIZE];   // [f][k] for this channel
    for (int i = threadIdx.x; i < N_FILT * KSIZE; i += 128) {
        int f = i / KSIZE, k = i - f * KSIZE;
        cw[i] = conv_w[(f * 2 + c) * KSIZE + k];
    }
    float wdrow[N_FILT];
    #pragma unroll
    for (int f = 0; f < N_FILT; f++) wdrow[f] = Wd[d * N_FILT + f];
    __syncthreads();

    #pragma unroll 4
    for (int k = 0; k < KSIZE; k++) {
        float s = 0.f;
        #pragma unroll
        for (int f = 0; f < N_FILT; f++) s = fmaf(cw[f * KSIZE + k], wdrow[f], s);
        g_G[(c * KSIZE + k) * ATT_DIM + d] = s;
    }
}

// ---------------- K1: pq = hidden @ Wq^T ----------------
// grid (4, B), 128 threads; block covers 32 d's, warp does 8 d serially
__global__ void pq_kernel(const float* __restrict__ hidden,
                          const float* __restrict__ Wq) {
    const int b = blockIdx.y;
    __shared__ float4 h4[RNN_DIM / 4];
    const float4* hsrc = reinterpret_cast<const float4*>(hidden + (size_t)b * RNN_DIM);
    for (int i = threadIdx.x; i < RNN_DIM / 4; i += 128) h4[i] = hsrc[i];
    __syncthreads();

    const int warp = threadIdx.x >> 5, lane = threadIdx.x & 31;
    #pragma unroll
    for (int jj = 0; jj < 8; jj++) {
        int d = blockIdx.x * 32 + warp * 8 + jj;
        const float4* wq4 = reinterpret_cast<const float4*>(Wq + (size_t)d * RNN_DIM);
        float s = 0.f;
        #pragma unroll
        for (int kk = 0; kk < 8; kk++) {
            float4 q = wq4[lane + 32 * kk], h = h4[lane + 32 * kk];
            s += q.x * h.x + q.y * h.y + q.z * h.z + q.w * h.w;
        }
        s = warp_sum(s);
        if (lane == 0) g_pq[b * ATT_DIM + d] = s;
    }
}

// ---------------- K2: fused stencil-GEMM + tanh + energy ----------------
// energies[b,t] = sum_d Wv[d] * tanh( pq[b,d] + pm[b,t,d] + sum_tap cat[c,t+k-15]*G[tap,d] )
// grid (T/TILE_T, B), 512 threads (16 warps). Warp w -> t = t0 + 8w .. +7.
// Lane owns d = 4*lane .. 4*lane+3.
__global__ __launch_bounds__(512, 1) void energies_kernel(
    const float* __restrict__ aw, const float* __restrict__ awc,
    const float* __restrict__ pm, const float* __restrict__ Wv)
{
    const int b  = blockIdx.y;
    const int t0 = blockIdx.x * TILE_T;
    const int tid = threadIdx.x;
    const int warp = tid >> 5, lane = tid & 31;
    const int wt0 = warp * 8;

    __shared__ __align__(16) float G_s[NTAPS * ATT_DIM];   // 31744 B
    __shared__ __align__(16) float cat_s[2][160];          // window 158 used
    __shared__ __align__(16) float pq_s[ATT_DIM];
    __shared__ __align__(16) float wv_s[ATT_DIM];

    for (int i = tid; i < NTAPS * ATT_DIM; i += 512) G_s[i] = g_G[i];
    for (int i = tid; i < 2 * 158; i += 512) {
        int c = i / 158, ii = i - c * 158;
        int t = t0 - PADW + ii;
        float v = 0.f;
        if (t >= 0 && t < TT) v = (c == 0 ? aw : awc)[(size_t)b * TT + t];
        cat_s[c][ii] = v;
    }
    if (tid < ATT_DIM) { pq_s[tid] = g_pq[b * ATT_DIM + tid]; wv_s[tid] = Wv[tid]; }
    __syncthreads();

    // accumulators: 8 t's x float4(d), stored as float2 pairs; init with pq
    float2 accA[8], accB[8];
    {
        float4 pq4 = reinterpret_cast<const float4*>(pq_s)[lane];
        #pragma unroll
        for (int j = 0; j < 8; j++) {
            accA[j] = make_float2(pq4.x, pq4.y);
            accB[j] = make_float2(pq4.z, pq4.w);
        }
    }

    const float4* Gs4 = reinterpret_cast<const float4*>(G_s);

    #pragma unroll
    for (int c = 0; c < 2; c++) {
        const float4* c4 = reinterpret_cast<const float4*>(&cat_s[c][0]);
        #pragma unroll
        for (int kb = 0; kb < 8; kb++) {
            const int k0 = kb * 4;
            const int NT = (kb == 7) ? 3 : 4;
            // window: cat[wt0+k0 .. wt0+k0+11], 16B aligned, broadcast
            const int base = (wt0 + k0) >> 2;
            float4 a0 = c4[base], a1 = c4[base + 1], a2 = c4[base + 2];
            float w[12] = {a0.x, a0.y, a0.z, a0.w,
                           a1.x, a1.y, a1.z, a1.w,
                           a2.x, a2.y, a2.z, a2.w};
            float2 w2[11];
            #pragma unroll
            for (int i = 0; i < 11; i++) w2[i] = make_float2(w[i], w[i]);

            #pragma unroll
            for (int dlt = 0; dlt < NT; dlt++) {
                const int tap = c * KSIZE + k0 + dlt;
                float4 g = Gs4[tap * 32 + lane];
                float2 gA = make_float2(g.x, g.y);
                float2 gB = make_float2(g.z, g.w);
                #pragma unroll
                for (int j = 0; j < 8; j++) {
                    accA[j] = fma2(gA, w2[dlt + j], accA[j]);
                    accB[j] = fma2(gB, w2[dlt + j], accB[j]);
                }
            }
        }
    }

    // epilogue: + pm, tanh, dot with Wv, warp-reduce over d
    const float4 wv4 = reinterpret_cast<const float4*>(wv_s)[lane];
    const float4* pm4 = reinterpret_cast<const float4*>(pm);

    #pragma unroll
    for (int j = 0; j < 8; j++) {
        int t = t0 + wt0 + j;
        float4 pmv = pm4[((size_t)b * TT + t) * 32 + lane];
        float x0 = tanh_hw(accA[j].x + pmv.x);
        float x1 = tanh_hw(accA[j].y + pmv.y);
        float x2 = tanh_hw(accB[j].x + pmv.z);
        float x3 = tanh_hw(accB[j].y + pmv.w);
        float p = x0 * wv4.x + x1 * wv4.y + x2 * wv4.z + x3 * wv4.w;
        p = warp_sum(p);
        if (lane == 0) g_energies[(size_t)b * TT + t] = p;
    }
}

// ---------------- K3: per-batch softmax over T ----------------
__global__ void softmax_kernel(const unsigned char* __restrict__ mask) {
    const int b = blockIdx.x, tid = threadIdx.x;  // 256 threads
    const int warp = tid >> 5, lane = tid & 31;
    __shared__ float red_m[8];
    __shared__ float red_s[8];
    __shared__ float s_max, s_sum;

    float v[8];
    #pragma unroll
    for (int i = 0; i < 8; i++) {
        int t = tid + 256 * i;
        float e = g_energies[(size_t)b * TT + t];
        if (mask[(size_t)b * TT + t]) e = __int_as_float(0xff800000);  // -inf
        v[i] = e;
    }

    float m = v[0];
    #pragma unroll
    for (int i = 1; i < 8; i++) m = fmaxf(m, v[i]);
    m = warp_max(m);
    if (lane == 0) red_m[warp] = m;
    __syncthreads();
    if (warp == 0) {
        float t = (lane < 8) ? red_m[lane] : __int_as_float(0xff800000);
        t = warp_max(t);
        if (lane == 0) s_max = t;
    }
    __syncthreads();
    const float M = s_max;

    float s = 0.f;
    #pragma unroll
    for (int i = 0; i < 8; i++) s += __expf(v[i] - M);
    s = warp_sum(s);
    if (lane == 0) red_s[warp] = s;
    __syncthreads();
    if (warp == 0) {
        float t = (lane < 8) ? red_s[lane] : 0.f;
        t = warp_sum(t);
        if (lane == 0) s_sum = t;
    }
    __syncthreads();
    const float inv = 1.0f / s_sum;

    #pragma unroll
    for (int i = 0; i < 8; i++) {
        int t = tid + 256 * i;
        g_w[(size_t)b * TT + t] = __expf(v[i] - M) * inv;
    }
}

// ---------------- K4: context partials, t-split ----------------
// grid (NSPLIT, B), 128 threads; thread = one float4 column chunk
__global__ __launch_bounds__(128) void context_kernel(const float* __restrict__ memory) {
    const int b = blockIdx.y, s = blockIdx.x;
    const int tid = threadIdx.x;
    const int TSEG = TT / NSPLIT;       // 64
    __shared__ float ws[TSEG];
    const int t0 = s * TSEG;
    if (tid < TSEG) ws[tid] = g_w[(size_t)b * TT + t0 + tid];
    __syncthreads();

    const float4* m4 = reinterpret_cast<const float4*>(memory + ((size_t)b * TT + t0) * EMB_DIM);
    float4 acc = make_float4(0.f, 0.f, 0.f, 0.f);
    #pragma unroll 16
    for (int t = 0; t < TSEG; t++) {
        float w = ws[t];
        float4 mv = m4[(size_t)t * (EMB_DIM / 4) + tid];
        acc.x += w * mv.x; acc.y += w * mv.y; acc.z += w * mv.z; acc.w += w * mv.w;
    }
    reinterpret_cast<float4*>(g_partial)[((size_t)(b * NSPLIT + s)) * (EMB_DIM / 4) + tid] = acc;
}

// ---------------- K5: reduce partials ----------------
__global__ void reduce_kernel(float* __restrict__ out) {
    int idx = blockIdx.x * blockDim.x + threadIdx.x;
    if (idx < BB * EMB_DIM) {
        int b = idx / EMB_DIM, e = idx - b * EMB_DIM;
        float s = 0.f;
        #pragma unroll
        for (int k = 0; k < NSPLIT; k++) s += g_partial[(b * NSPLIT + k) * EMB_DIM + e];
        out[idx] = s;
    }
}

// ---------------- launch ----------------
extern "C" void kernel_launch(void* const* d_in, const int* in_sizes, int n_in,
                              void* d_out, int out_size) {
    const float*         hidden = (const float*)d_in[0];          // (B, RNN_DIM)
    const float*         memory = (const float*)d_in[1];          // (B, T, EMB_DIM)
    const float*         pm     = (const float*)d_in[2];          // (B, T, ATT_DIM)
    const float*         aw     = (const float*)d_in[3];          // (B, T)
    const float*         awc    = (const float*)d_in[4];          // (B, T)
    const float*         Wq     = (const float*)d_in[5];          // (ATT_DIM, RNN_DIM)
    const float*         conv_w = (const float*)d_in[6];          // (N_FILT, 2, KSIZE)
    const float*         Wd     = (const float*)d_in[7];          // (ATT_DIM, N_FILT)
    const float*         Wv     = (const float*)d_in[8];          // (ATT_DIM,)
    const unsigned char* mask   = (const unsigned char*)d_in[9];  // (B, T) bool
    float* out = (float*)d_out;

    G_kernel<<<2, 128>>>(conv_w, Wd);

    dim3 g1(4, BB);
    pq_kernel<<<g1, 128>>>(hidden, Wq);

    dim3 g2(TT / TILE_T, BB);
    energies_kernel<<<g2, 512>>>(aw, awc, pm, Wv);

    softmax_kernel<<<BB, 256>>>(mask);

    dim3 g4(NSPLIT, BB);
    context_kernel<<<g4, 128>>>(memory);

    reduce_kernel<<<(BB * EMB_DIM + 255) / 256, 256>>>(out);
}

// round 9
// speedup vs baseline: 1.3400x; 1.0124x over previous
#include <cuda_runtime.h>
#include <cstdint>

// ---------------- problem constants ----------------
#define BB       64
#define TT       2048
#define RNN_DIM  1024
#define EMB_DIM  512
#define ATT_DIM  128
#define N_FILT   32
#define KSIZE    31
#define PADW     15
#define TILE_T   128
#define NSPLIT   32          // t-splits for context kernel
#define NTAPS    62          // 2 channels x 31 taps

// ---------------- scratch (no cudaMalloc allowed) ----------------
__device__ float g_pq[BB * ATT_DIM];
__device__ float g_G[NTAPS * ATT_DIM];       // fused conv x Wd matrix
__device__ float g_energies[BB * TT];
__device__ float g_w[BB * TT];
__device__ float g_partial[BB * NSPLIT * EMB_DIM];

// ---------------- helpers ----------------
__device__ __forceinline__ float2 fma2(float2 a, float2 b, float2 c) {
    unsigned long long ra = *reinterpret_cast<unsigned long long*>(&a);
    unsigned long long rb = *reinterpret_cast<unsigned long long*>(&b);
    unsigned long long rc = *reinterpret_cast<unsigned long long*>(&c);
    unsigned long long rd;
    asm("fma.rn.f32x2 %0, %1, %2, %3;" : "=l"(rd) : "l"(ra), "l"(rb), "l"(rc));
    return *reinterpret_cast<float2*>(&rd);
}

__device__ __forceinline__ float tanh_hw(float x) {
    float y;
    asm("tanh.approx.f32 %0, %1;" : "=f"(y) : "f"(x));
    return y;
}

__device__ __forceinline__ float warp_max(float x) {
    #pragma unroll
    for (int o = 16; o; o >>= 1) x = fmaxf(x, __shfl_xor_sync(0xffffffffu, x, o));
    return x;
}
__device__ __forceinline__ float warp_sum(float x) {
    #pragma unroll
    for (int o = 16; o; o >>= 1) x += __shfl_xor_sync(0xffffffffu, x, o);
    return x;
}

// ---------------- K0: G[(c,k),d] = sum_f conv_w[f,c,k] * Wd[d,f] ----------------
// grid 2 (c), 128 threads (d)
__global__ void G_kernel(const float* __restrict__ conv_w,
                         const float* __restrict__ Wd) {
    const int c = blockIdx.x, d = threadIdx.x;
    __shared__ float cw[N_FILT * KSIZE];   // [f][k] for this channel
    for (int i = threadIdx.x; i < N_FILT * KSIZE; i += 128) {
        int f = i / KSIZE, k = i - f * KSIZE;
        cw[i] = conv_w[(f * 2 + c) * KSIZE + k];
    }
    float wdrow[N_FILT];
    #pragma unroll
    for (int f = 0; f < N_FILT; f++) wdrow[f] = Wd[d * N_FILT + f];
    __syncthreads();

    #pragma unroll 4
    for (int k = 0; k < KSIZE; k++) {
        float s = 0.f;
        #pragma unroll
        for (int f = 0; f < N_FILT; f++) s = fmaf(cw[f * KSIZE + k], wdrow[f], s);
        g_G[(c * KSIZE + k) * ATT_DIM + d] = s;
    }
}

// ---------------- K1: pq = hidden @ Wq^T ----------------
// grid (4, B), 128 threads; block covers 32 d's, warp does 8 d serially
__global__ void pq_kernel(const float* __restrict__ hidden,
                          const float* __restrict__ Wq) {
    const int b = blockIdx.y;
    __shared__ float4 h4[RNN_DIM / 4];
    const float4* hsrc = reinterpret_cast<const float4*>(hidden + (size_t)b * RNN_DIM);
    for (int i = threadIdx.x; i < RNN_DIM / 4; i += 128) h4[i] = hsrc[i];
    __syncthreads();

    const int warp = threadIdx.x >> 5, lane = threadIdx.x & 31;
    #pragma unroll
    for (int jj = 0; jj < 8; jj++) {
        int d = blockIdx.x * 32 + warp * 8 + jj;
        const float4* wq4 = reinterpret_cast<const float4*>(Wq + (size_t)d * RNN_DIM);
        float s = 0.f;
        #pragma unroll
        for (int kk = 0; kk < 8; kk++) {
            float4 q = wq4[lane + 32 * kk], h = h4[lane + 32 * kk];
            s += q.x * h.x + q.y * h.y + q.z * h.z + q.w * h.w;
        }
        s = warp_sum(s);
        if (lane == 0) g_pq[b * ATT_DIM + d] = s;
    }
}

// ---------------- K2: fused stencil-GEMM + tanh + energy ----------------
// energies[b,t] = sum_d Wv[d] * tanh( pq[b,d] + pm[b,t,d] + sum_tap cat[c,t+k-15]*G[tap,d] )
// grid (T/TILE_T, B), 512 threads (16 warps). Warp w -> t = t0 + 8w .. +7.
// Lane owns d = 4*lane .. 4*lane+3.
__global__ __launch_bounds__(512, 1) void energies_kernel(
    const float* __restrict__ aw, const float* __restrict__ awc,
    const float* __restrict__ pm, const float* __restrict__ Wv)
{
    const int b  = blockIdx.y;
    const int t0 = blockIdx.x * TILE_T;
    const int tid = threadIdx.x;
    const int warp = tid >> 5, lane = tid & 31;
    const int wt0 = warp * 8;

    __shared__ __align__(16) float G_s[NTAPS * ATT_DIM];   // 31744 B
    __shared__ __align__(16) float cat_s[2][160];          // window 158 used
    __shared__ __align__(16) float pq_s[ATT_DIM];
    __shared__ __align__(16) float wv_s[ATT_DIM];

    for (int i = tid; i < NTAPS * ATT_DIM; i += 512) G_s[i] = g_G[i];
    for (int i = tid; i < 2 * 158; i += 512) {
        int c = i / 158, ii = i - c * 158;
        int t = t0 - PADW + ii;
        float v = 0.f;
        if (t >= 0 && t < TT) v = (c == 0 ? aw : awc)[(size_t)b * TT + t];
        cat_s[c][ii] = v;
    }
    if (tid < ATT_DIM) { pq_s[tid] = g_pq[b * ATT_DIM + tid]; wv_s[tid] = Wv[tid]; }
    __syncthreads();

    // accumulators: 8 t's x float4(d), stored as float2 pairs; init with pq
    float2 accA[8], accB[8];
    {
        float4 pq4 = reinterpret_cast<const float4*>(pq_s)[lane];
        #pragma unroll
        for (int j = 0; j < 8; j++) {
            accA[j] = make_float2(pq4.x, pq4.y);
            accB[j] = make_float2(pq4.z, pq4.w);
        }
    }

    const float4* Gs4 = reinterpret_cast<const float4*>(G_s);

    #pragma unroll
    for (int c = 0; c < 2; c++) {
        const float4* c4 = reinterpret_cast<const float4*>(&cat_s[c][0]);
        #pragma unroll
        for (int kb = 0; kb < 8; kb++) {
            const int k0 = kb * 4;
            const int NT = (kb == 7) ? 3 : 4;
            // window: cat[wt0+k0 .. wt0+k0+11], 16B aligned, broadcast
            const int base = (wt0 + k0) >> 2;
            float4 a0 = c4[base], a1 = c4[base + 1], a2 = c4[base + 2];
            float w[12] = {a0.x, a0.y, a0.z, a0.w,
                           a1.x, a1.y, a1.z, a1.w,
                           a2.x, a2.y, a2.z, a2.w};
            float2 w2[11];
            #pragma unroll
            for (int i = 0; i < 11; i++) w2[i] = make_float2(w[i], w[i]);

            #pragma unroll
            for (int dlt = 0; dlt < NT; dlt++) {
                const int tap = c * KSIZE + k0 + dlt;
                float4 g = Gs4[tap * 32 + lane];
                float2 gA = make_float2(g.x, g.y);
                float2 gB = make_float2(g.z, g.w);
                #pragma unroll
                for (int j = 0; j < 8; j++) {
                    accA[j] = fma2(gA, w2[dlt + j], accA[j]);
                    accB[j] = fma2(gB, w2[dlt + j], accB[j]);
                }
            }
        }
    }

    // epilogue: + pm, tanh, dot with Wv, warp-reduce over d
    const float4 wv4 = reinterpret_cast<const float4*>(wv_s)[lane];
    const float4* pm4 = reinterpret_cast<const float4*>(pm);

    #pragma unroll
    for (int j = 0; j < 8; j++) {
        int t = t0 + wt0 + j;
        float4 pmv = pm4[((size_t)b * TT + t) * 32 + lane];
        float x0 = tanh_hw(accA[j].x + pmv.x);
        float x1 = tanh_hw(accA[j].y + pmv.y);
        float x2 = tanh_hw(accB[j].x + pmv.z);
        float x3 = tanh_hw(accB[j].y + pmv.w);
        float p = x0 * wv4.x + x1 * wv4.y + x2 * wv4.z + x3 * wv4.w;
        p = warp_sum(p);
        if (lane == 0) g_energies[(size_t)b * TT + t] = p;
    }
}

// ---------------- K3: per-batch softmax over T ----------------
__global__ void softmax_kernel(const unsigned char* __restrict__ mask) {
    const int b = blockIdx.x, tid = threadIdx.x;  // 256 threads
    const int warp = tid >> 5, lane = tid & 31;
    __shared__ float red_m[8];
    __shared__ float red_s[8];
    __shared__ float s_max, s_sum;

    float v[8];
    #pragma unroll
    for (int i = 0; i < 8; i++) {
        int t = tid + 256 * i;
        float e = g_energies[(size_t)b * TT + t];
        if (mask[(size_t)b * TT + t]) e = __int_as_float(0xff800000);  // -inf
        v[i] = e;
    }

    float m = v[0];
    #pragma unroll
    for (int i = 1; i < 8; i++) m = fmaxf(m, v[i]);
    m = warp_max(m);
    if (lane == 0) red_m[warp] = m;
    __syncthreads();
    if (warp == 0) {
        float t = (lane < 8) ? red_m[lane] : __int_as_float(0xff800000);
        t = warp_max(t);
        if (lane == 0) s_max = t;
    }
    __syncthreads();
    const float M = s_max;

    float s = 0.f;
    #pragma unroll
    for (int i = 0; i < 8; i++) s += __expf(v[i] - M);
    s = warp_sum(s);
    if (lane == 0) red_s[warp] = s;
    __syncthreads();
    if (warp == 0) {
        float t = (lane < 8) ? red_s[lane] : 0.f;
        t = warp_sum(t);
        if (lane == 0) s_sum = t;
    }
    __syncthreads();
    const float inv = 1.0f / s_sum;

    #pragma unroll
    for (int i = 0; i < 8; i++) {
        int t = tid + 256 * i;
        g_w[(size_t)b * TT + t] = __expf(v[i] - M) * inv;
    }
}

// ---------------- K4: context partials, t-split ----------------
// grid (NSPLIT, B), 128 threads; thread = one float4 column chunk
__global__ __launch_bounds__(128) void context_kernel(const float* __restrict__ memory) {
    const int b = blockIdx.y, s = blockIdx.x;
    const int tid = threadIdx.x;
    const int TSEG = TT / NSPLIT;       // 64
    __shared__ float ws[TSEG];
    const int t0 = s * TSEG;
    if (tid < TSEG) ws[tid] = g_w[(size_t)b * TT + t0 + tid];
    __syncthreads();

    const float4* m4 = reinterpret_cast<const float4*>(memory + ((size_t)b * TT + t0) * EMB_DIM);
    float4 acc = make_float4(0.f, 0.f, 0.f, 0.f);
    #pragma unroll 16
    for (int t = 0; t < TSEG; t++) {
        float w = ws[t];
        float4 mv = m4[(size_t)t * (EMB_DIM / 4) + tid];
        acc.x += w * mv.x; acc.y += w * mv.y; acc.z += w * mv.z; acc.w += w * mv.w;
    }
    reinterpret_cast<float4*>(g_partial)[((size_t)(b * NSPLIT + s)) * (EMB_DIM / 4) + tid] = acc;
}

// ---------------- K5: reduce partials ----------------
__global__ void reduce_kernel(float* __restrict__ out) {
    int idx = blockIdx.x * blockDim.x + threadIdx.x;
    if (idx < BB * EMB_DIM) {
        int b = idx / EMB_DIM, e = idx - b * EMB_DIM;
        float s = 0.f;
        #pragma unroll
        for (int k = 0; k < NSPLIT; k++) s += g_partial[(b * NSPLIT + k) * EMB_DIM + e];
        out[idx] = s;
    }
}

// ---------------- launch ----------------
extern "C" void kernel_launch(void* const* d_in, const int* in_sizes, int n_in,
                              void* d_out, int out_size) {
    const float*         hidden = (const float*)d_in[0];          // (B, RNN_DIM)
    const float*         memory = (const float*)d_in[1];          // (B, T, EMB_DIM)
    const float*         pm     = (const float*)d_in[2];          // (B, T, ATT_DIM)
    const float*         aw     = (const float*)d_in[3];          // (B, T)
    const float*         awc    = (const float*)d_in[4];          // (B, T)
    const float*         Wq     = (const float*)d_in[5];          // (ATT_DIM, RNN_DIM)
    const float*         conv_w = (const float*)d_in[6];          // (N_FILT, 2, KSIZE)
    const float*         Wd     = (const float*)d_in[7];          // (ATT_DIM, N_FILT)
    const float*         Wv     = (const float*)d_in[8];          // (ATT_DIM,)
    const unsigned char* mask   = (const unsigned char*)d_in[9];  // (B, T) bool
    float* out = (float*)d_out;

    G_kernel<<<2, 128>>>(conv_w, Wd);

    dim3 g1(4, BB);
    pq_kernel<<<g1, 128>>>(hidden, Wq);

    dim3 g2(TT / TILE_T, BB);
    energies_kernel<<<g2, 512>>>(aw, awc, pm, Wv);

    softmax_kernel<<<BB, 256>>>(mask);

    dim3 g4(NSPLIT, BB);
    context_kernel<<<g4, 128>>>(memory);

    reduce_kernel<<<(BB * EMB_DIM + 255) / 256, 256>>>(out);
}

// round 10
// speedup vs baseline: 1.4602x; 1.0897x over previous
#include <cuda_runtime.h>
#include <cstdint>

// ---------------- problem constants ----------------
#define BB       64
#define TT       2048
#define RNN_DIM  1024
#define EMB_DIM  512
#define ATT_DIM  128
#define N_FILT   32
#define KSIZE    31
#define PADW     15
#define TILE_T   128
#define NSPLIT   32          // t-splits for context kernel
#define NTAPS    62          // 2 channels x 31 taps

// ---------------- scratch (no cudaMalloc allowed) ----------------
__device__ float g_pq[BB * ATT_DIM];
__device__ float g_G[NTAPS * ATT_DIM];       // fused conv x Wd matrix
__device__ float g_energies[BB * TT];

// ---------------- helpers ----------------
__device__ __forceinline__ float2 fma2(float2 a, float2 b, float2 c) {
    unsigned long long ra = *reinterpret_cast<unsigned long long*>(&a);
    unsigned long long rb = *reinterpret_cast<unsigned long long*>(&b);
    unsigned long long rc = *reinterpret_cast<unsigned long long*>(&c);
    unsigned long long rd;
    asm("fma.rn.f32x2 %0, %1, %2, %3;" : "=l"(rd) : "l"(ra), "l"(rb), "l"(rc));
    return *reinterpret_cast<float2*>(&rd);
}

__device__ __forceinline__ float tanh_hw(float x) {
    float y;
    asm("tanh.approx.f32 %0, %1;" : "=f"(y) : "f"(x));
    return y;
}

__device__ __forceinline__ float warp_max(float x) {
    #pragma unroll
    for (int o = 16; o; o >>= 1) x = fmaxf(x, __shfl_xor_sync(0xffffffffu, x, o));
    return x;
}
__device__ __forceinline__ float warp_sum(float x) {
    #pragma unroll
    for (int o = 16; o; o >>= 1) x += __shfl_xor_sync(0xffffffffu, x, o);
    return x;
}

// ---------------- K1: merged init ----------------
// blocks 0..1   : G[(c,k),d] = sum_f conv_w[f,c,k] * Wd[d,f]   (c = blockIdx.x)
// blocks 2..257 : pq = hidden @ Wq^T  (b = (bid-2)/4, quarter = (bid-2)%4)
//                 and zero 128 floats of out each.
__global__ __launch_bounds__(128) void init_kernel(
    const float* __restrict__ conv_w, const float* __restrict__ Wd,
    const float* __restrict__ hidden, const float* __restrict__ Wq,
    float* __restrict__ out)
{
    const int bid = blockIdx.x;
    if (bid < 2) {
        // ---- G ----
        const int c = bid, d = threadIdx.x;
        __shared__ float cw[N_FILT * KSIZE];
        for (int i = threadIdx.x; i < N_FILT * KSIZE; i += 128) {
            int f = i / KSIZE, k = i - f * KSIZE;
            cw[i] = conv_w[(f * 2 + c) * KSIZE + k];
        }
        float wdrow[N_FILT];
        #pragma unroll
        for (int f = 0; f < N_FILT; f++) wdrow[f] = Wd[d * N_FILT + f];
        __syncthreads();
        #pragma unroll 4
        for (int k = 0; k < KSIZE; k++) {
            float s = 0.f;
            #pragma unroll
            for (int f = 0; f < N_FILT; f++) s = fmaf(cw[f * KSIZE + k], wdrow[f], s);
            g_G[(c * KSIZE + k) * ATT_DIM + d] = s;
        }
        return;
    }

    // ---- pq + zero out ----
    const int pb = bid - 2;                   // 0..255
    out[pb * 128 + threadIdx.x] = 0.f;        // zero BB*EMB_DIM = 32768 floats

    const int b = pb >> 2, quarter = pb & 3;
    __shared__ float4 h4[RNN_DIM / 4];
    const float4* hsrc = reinterpret_cast<const float4*>(hidden + (size_t)b * RNN_DIM);
    for (int i = threadIdx.x; i < RNN_DIM / 4; i += 128) h4[i] = hsrc[i];
    __syncthreads();

    const int warp = threadIdx.x >> 5, lane = threadIdx.x & 31;
    #pragma unroll
    for (int jj = 0; jj < 8; jj++) {
        int d = quarter * 32 + warp * 8 + jj;
        const float4* wq4 = reinterpret_cast<const float4*>(Wq + (size_t)d * RNN_DIM);
        float s = 0.f;
        #pragma unroll
        for (int kk = 0; kk < 8; kk++) {
            float4 q = wq4[lane + 32 * kk], h = h4[lane + 32 * kk];
            s += q.x * h.x + q.y * h.y + q.z * h.z + q.w * h.w;
        }
        s = warp_sum(s);
        if (lane == 0) g_pq[b * ATT_DIM + d] = s;
    }
}

// ---------------- K2: fused stencil-GEMM + tanh + energy (+mask) ----------------
// energies[b,t] = sum_d Wv[d] * tanh( pq[b,d] + pm[b,t,d] + sum_tap cat[c,t+k-15]*G[tap,d] )
// grid (T/TILE_T, B), 512 threads (16 warps). Warp w -> t = t0 + 8w .. +7.
// Lane owns d = 4*lane .. 4*lane+3.
__global__ __launch_bounds__(512, 1) void energies_kernel(
    const float* __restrict__ aw, const float* __restrict__ awc,
    const float* __restrict__ pm, const float* __restrict__ Wv,
    const unsigned char* __restrict__ mask)
{
    const int b  = blockIdx.y;
    const int t0 = blockIdx.x * TILE_T;
    const int tid = threadIdx.x;
    const int warp = tid >> 5, lane = tid & 31;
    const int wt0 = warp * 8;

    // prefetch pm for this warp's 8 t's NOW — hides DRAM latency under the FMA loop
    float4 pmr[8];
    {
        const float4* pm4 = reinterpret_cast<const float4*>(pm);
        const size_t base = ((size_t)b * TT + t0 + wt0) * 32 + lane;
        #pragma unroll
        for (int j = 0; j < 8; j++) pmr[j] = pm4[base + (size_t)j * 32];
    }

    __shared__ __align__(16) float G_s[NTAPS * ATT_DIM];   // 31744 B
    __shared__ __align__(16) float cat_s[2][160];
    __shared__ __align__(16) float pq_s[ATT_DIM];
    __shared__ __align__(16) float wv_s[ATT_DIM];

    for (int i = tid; i < NTAPS * ATT_DIM; i += 512) G_s[i] = g_G[i];
    for (int i = tid; i < 2 * 158; i += 512) {
        int c = i / 158, ii = i - c * 158;
        int t = t0 - PADW + ii;
        float v = 0.f;
        if (t >= 0 && t < TT) v = (c == 0 ? aw : awc)[(size_t)b * TT + t];
        cat_s[c][ii] = v;
    }
    if (tid < ATT_DIM) { pq_s[tid] = g_pq[b * ATT_DIM + tid]; wv_s[tid] = Wv[tid]; }
    __syncthreads();

    float2 accA[8], accB[8];
    #pragma unroll
    for (int j = 0; j < 8; j++) {
        accA[j] = make_float2(0.f, 0.f);
        accB[j] = make_float2(0.f, 0.f);
    }

    const float4* Gs4 = reinterpret_cast<const float4*>(G_s);

    #pragma unroll
    for (int c = 0; c < 2; c++) {
        const float4* c4 = reinterpret_cast<const float4*>(&cat_s[c][0]);
        #pragma unroll
        for (int kb = 0; kb < 8; kb++) {
            const int k0 = kb * 4;
            const int NT = (kb == 7) ? 3 : 4;
            const int base = (wt0 + k0) >> 2;
            float4 a0 = c4[base], a1 = c4[base + 1], a2 = c4[base + 2];
            float w[12] = {a0.x, a0.y, a0.z, a0.w,
                           a1.x, a1.y, a1.z, a1.w,
                           a2.x, a2.y, a2.z, a2.w};
            float2 w2[11];
            #pragma unroll
            for (int i = 0; i < 11; i++) w2[i] = make_float2(w[i], w[i]);

            #pragma unroll
            for (int dlt = 0; dlt < NT; dlt++) {
                const int tap = c * KSIZE + k0 + dlt;
                float4 g = Gs4[tap * 32 + lane];
                float2 gA = make_float2(g.x, g.y);
                float2 gB = make_float2(g.z, g.w);
                #pragma unroll
                for (int j = 0; j < 8; j++) {
                    accA[j] = fma2(gA, w2[dlt + j], accA[j]);
                    accB[j] = fma2(gB, w2[dlt + j], accB[j]);
                }
            }
        }
    }

    // epilogue: + pq + pm, tanh, dot with Wv, warp-reduce over d, apply mask
    const float4 wv4 = reinterpret_cast<const float4*>(wv_s)[lane];
    const float4 pq4 = reinterpret_cast<const float4*>(pq_s)[lane];

    #pragma unroll
    for (int j = 0; j < 8; j++) {
        int t = t0 + wt0 + j;
        float x0 = tanh_hw(accA[j].x + pq4.x + pmr[j].x);
        float x1 = tanh_hw(accA[j].y + pq4.y + pmr[j].y);
        float x2 = tanh_hw(accB[j].x + pq4.z + pmr[j].z);
        float x3 = tanh_hw(accB[j].y + pq4.w + pmr[j].w);
        float p = x0 * wv4.x + x1 * wv4.y + x2 * wv4.z + x3 * wv4.w;
        p = warp_sum(p);
        if (lane == 0) {
            if (mask[(size_t)b * TT + t]) p = __int_as_float(0xff800000);  // -inf
            g_energies[(size_t)b * TT + t] = p;
        }
    }
}

// ---------------- K3: fused softmax + context partial + atomic reduce ----------------
// grid (NSPLIT, B), 128 threads. Each block recomputes softmax stats (8 KB,
// L2-resident) then does the weighted GEMV for its 64-t segment, REDG into out.
__global__ __launch_bounds__(128) void context_kernel(
    const float* __restrict__ memory, float* __restrict__ out)
{
    const int b = blockIdx.y, s = blockIdx.x;
    const int tid = threadIdx.x;
    const int warp = tid >> 5, lane = tid & 31;
    const int TSEG = TT / NSPLIT;       // 64

    __shared__ float red[4];
    __shared__ float s_max, s_sum;
    __shared__ float ws[TSEG];

    // ---- softmax stats over all T of this batch ----
    const float4* e4 = reinterpret_cast<const float4*>(&g_energies[(size_t)b * TT]);
    float4 v[4];
    #pragma unroll
    for (int i = 0; i < 4; i++) v[i] = e4[tid + 128 * i];

    float m = v[0].x;
    #pragma unroll
    for (int i = 0; i < 4; i++) {
        m = fmaxf(m, fmaxf(fmaxf(v[i].x, v[i].y), fmaxf(v[i].z, v[i].w)));
    }
    m = warp_max(m);
    if (lane == 0) red[warp] = m;
    __syncthreads();
    if (tid == 0)
        s_max = fmaxf(fmaxf(red[0], red[1]), fmaxf(red[2], red[3]));
    __syncthreads();
    const float M = s_max;

    float sum = 0.f;
    #pragma unroll
    for (int i = 0; i < 4; i++) {
        sum += __expf(v[i].x - M) + __expf(v[i].y - M)
             + __expf(v[i].z - M) + __expf(v[i].w - M);
    }
    sum = warp_sum(sum);
    if (lane == 0) red[warp] = sum;
    __syncthreads();
    if (tid == 0)
        s_sum = red[0] + red[1] + red[2] + red[3];
    __syncthreads();
    const float inv = 1.0f / s_sum;

    // ---- weights for this segment ----
    const int t0 = s * TSEG;
    if (tid < TSEG)
        ws[tid] = __expf(g_energies[(size_t)b * TT + t0 + tid] - M) * inv;
    __syncthreads();

    // ---- weighted GEMV over the segment ----
    const float4* m4 = reinterpret_cast<const float4*>(memory + ((size_t)b * TT + t0) * EMB_DIM);
    float4 acc = make_float4(0.f, 0.f, 0.f, 0.f);
    #pragma unroll 16
    for (int t = 0; t < TSEG; t++) {
        float w = ws[t];
        float4 mv = m4[(size_t)t * (EMB_DIM / 4) + tid];
        acc.x += w * mv.x; acc.y += w * mv.y; acc.z += w * mv.z; acc.w += w * mv.w;
    }

    float* o = out + (size_t)b * EMB_DIM + tid * 4;
    atomicAdd(o + 0, acc.x);
    atomicAdd(o + 1, acc.y);
    atomicAdd(o + 2, acc.z);
    atomicAdd(o + 3, acc.w);
}

// ---------------- launch ----------------
extern "C" void kernel_launch(void* const* d_in, const int* in_sizes, int n_in,
                              void* d_out, int out_size) {
    const float*         hidden = (const float*)d_in[0];          // (B, RNN_DIM)
    const float*         memory = (const float*)d_in[1];          // (B, T, EMB_DIM)
    const float*         pm     = (const float*)d_in[2];          // (B, T, ATT_DIM)
    const float*         aw     = (const float*)d_in[3];          // (B, T)
    const float*         awc    = (const float*)d_in[4];          // (B, T)
    const float*         Wq     = (const float*)d_in[5];          // (ATT_DIM, RNN_DIM)
    const float*         conv_w = (const float*)d_in[6];          // (N_FILT, 2, KSIZE)
    const float*         Wd     = (const float*)d_in[7];          // (ATT_DIM, N_FILT)
    const float*         Wv     = (const float*)d_in[8];          // (ATT_DIM,)
    const unsigned char* mask   = (const unsigned char*)d_in[9];  // (B, T) bool
    float* out = (float*)d_out;

    init_kernel<<<2 + 4 * BB, 128>>>(conv_w, Wd, hidden, Wq, out);

    dim3 g2(TT / TILE_T, BB);
    energies_kernel<<<g2, 512>>>(aw, awc, pm, Wv, mask);

    dim3 g3(NSPLIT, BB);
    context_kernel<<<g3, 128>>>(memory, out);
}